// round 9
// baseline (speedup 1.0000x reference)
#include <cuda_runtime.h>
#include <cuda_bf16.h>
#include <cstdint>

#define NLEVELS 12
#define HASH_MASK 0x7FFFFu
#define HASH_SIZE 524288
#define WROW 144              // bytes per A-buffer row (conflict-free for frag LDS)

__device__ __forceinline__ float lrelu(float v) { return fmaxf(v, 0.01f * v); }

// split w into bf16 hi + bf16 lo(residual)
__device__ __forceinline__ void hilo(float w, unsigned short& h, unsigned short& l) {
    __nv_bfloat16 hb = __float2bfloat16(w);
    h = __bfloat16_as_ushort(hb);
    l = __bfloat16_as_ushort(__float2bfloat16(w - __bfloat162float(hb)));
}
// pack (a,b) into hi-word/lo-word bf16x2 pair for both hi and lo parts
__device__ __forceinline__ void pkhl(float a, float b, uint32_t& hi, uint32_t& lo) {
    unsigned short ha, la, hb, lb;
    hilo(a, ha, la); hilo(b, hb, lb);
    hi = (uint32_t)ha | ((uint32_t)hb << 16);
    lo = (uint32_t)la | ((uint32_t)lb << 16);
}

__device__ __forceinline__ void mma_bf16(float& d0, float& d1, float& d2, float& d3,
                                         const uint32_t* A, const uint32_t* B) {
    asm volatile(
        "mma.sync.aligned.m16n8k16.row.col.f32.bf16.bf16.f32 "
        "{%0,%1,%2,%3}, {%4,%5,%6,%7}, {%8,%9}, {%0,%1,%2,%3};"
        : "+f"(d0), "+f"(d1), "+f"(d2), "+f"(d3)
        : "r"(A[0]), "r"(A[1]), "r"(A[2]), "r"(A[3]), "r"(B[0]), "r"(B[1]));
}

__global__ void __launch_bounds__(128)
nhgrid_mma(const float* __restrict__ x,
           const float* __restrict__ tables,
           const float* __restrict__ W1, const float* __restrict__ b1,
           const float* __restrict__ W2, const float* __restrict__ b2,
           const float* __restrict__ W3, const float* __restrict__ b3,
           const float* __restrict__ W4, const float* __restrict__ b4,
           float* __restrict__ out, int n, int ntiles)
{
    __shared__ __align__(16) char sb[4 * 32 * WROW];

    const int tid  = threadIdx.x;
    const int lane = tid & 31;
    const int warp = tid >> 5;
    char* wb = sb + warp * 32 * WROW;

    const int qr = lane >> 2;        // quad row 0..7
    const int qc = lane & 3;         // quad col 0..3

    // ---------------- weight fragments (registers, loaded once) ----------------
    // B frag (col layout, m16n8k16): b0 = {k=qc*2, k=qc*2+1} @ n=qr ; b1 = k+8,+9
    uint32_t B1h[4][2][2], B1l[4][2][2];   // [ntile][kstep][reg]
    uint32_t B2h[2][2][2], B2l[2][2][2];
    uint32_t B3h[2], B3l[2];
#pragma unroll
    for (int nt = 0; nt < 4; nt++)
#pragma unroll
        for (int ks = 0; ks < 2; ks++) {
            const int nn = nt * 8 + qr, k = ks * 16 + qc * 2;
            const float w00 = (k     < 24) ? W1[nn * 24 + k]     : 0.f;
            const float w01 = (k + 1 < 24) ? W1[nn * 24 + k + 1] : 0.f;
            const float w08 = (k + 8 < 24) ? W1[nn * 24 + k + 8] : 0.f;
            const float w09 = (k + 9 < 24) ? W1[nn * 24 + k + 9] : 0.f;
            pkhl(w00, w01, B1h[nt][ks][0], B1l[nt][ks][0]);
            pkhl(w08, w09, B1h[nt][ks][1], B1l[nt][ks][1]);
        }
#pragma unroll
    for (int nt = 0; nt < 2; nt++)
#pragma unroll
        for (int ks = 0; ks < 2; ks++) {
            const int nn = nt * 8 + qr, k = ks * 16 + qc * 2;
            pkhl(W2[nn * 32 + k],     W2[nn * 32 + k + 1], B2h[nt][ks][0], B2l[nt][ks][0]);
            pkhl(W2[nn * 32 + k + 8], W2[nn * 32 + k + 9], B2h[nt][ks][1], B2l[nt][ks][1]);
        }
    {
        const int nn = qr, k = qc * 2;
        pkhl(W3[nn * 16 + k],     W3[nn * 16 + k + 1], B3h[0], B3l[0]);
        pkhl(W3[nn * 16 + k + 8], W3[nn * 16 + k + 9], B3h[1], B3l[1]);
    }
    // biases / W4 per-lane
    float bl1[4][2], bl2[2][2], bl3[2];
#pragma unroll
    for (int nt = 0; nt < 4; nt++) {
        bl1[nt][0] = b1[nt * 8 + qc * 2];
        bl1[nt][1] = b1[nt * 8 + qc * 2 + 1];
    }
#pragma unroll
    for (int nt = 0; nt < 2; nt++) {
        bl2[nt][0] = b2[nt * 8 + qc * 2];
        bl2[nt][1] = b2[nt * 8 + qc * 2 + 1];
    }
    bl3[0] = b3[qc * 2]; bl3[1] = b3[qc * 2 + 1];
    const float w4a = W4[qc * 2], w4b = W4[qc * 2 + 1];
    const float b4v = b4[0];

    const float sp[NLEVELS] = {1.f, 2.f, 3.f, 5.f, 9.f, 15.f,
                               24.f, 39.f, 62.f, 99.f, 159.f, 256.f};

    // A-fragment loader: part = 0 (hi) or 64 (lo); ks in {0,1}
    auto lda = [&](int mt, int ks, int part, uint32_t* A) {
        const char* p = wb + (mt * 16 + qr) * WROW + part + ks * 32 + qc * 4;
        A[0] = *(const uint32_t*)p;
        A[1] = *(const uint32_t*)(p + 8 * WROW);
        A[2] = *(const uint32_t*)(p + 16);
        A[3] = *(const uint32_t*)(p + 8 * WROW + 16);
    };

    for (int tile = blockIdx.x; tile < ntiles; tile += gridDim.x) {
        const int tb = tile * 128 + warp * 32;
        const int point = tb + lane;
        const int pidx = point < n ? point : (n - 1);

        // ---- hash + gather (12 loads in flight) ----
        const float2 xv = __ldg(((const float2*)x) + pidx);
        const float x0 = xv.x * 0.5f + 0.5f;
        const float x1 = xv.y * 0.5f + 0.5f;
        unsigned h[NLEVELS];
#pragma unroll
        for (int l = 0; l < NLEVELS; l++) {
            const int d0 = (int)floorf(x0 * sp[l]);
            const int d1 = (int)floorf(x1 * sp[l]);
            h[l] = ((unsigned)d0 * 73856093u + (unsigned)d1 * 19349663u) & HASH_MASK;
        }
        float2 ft[NLEVELS];
#pragma unroll
        for (int l = 0; l < NLEVELS; l++)
            ft[l] = __ldg(((const float2*)tables) + (size_t)l * HASH_SIZE + h[l]);

        // ---- store features: row = lane; hi bytes[0:64), lo bytes[64:128) ----
        {
            char* rb = wb + lane * WROW;
#pragma unroll
            for (int l = 0; l < NLEVELS; l++) {
                uint32_t hi, lo;
                pkhl(ft[l].x, ft[l].y, hi, lo);
                *(uint32_t*)(rb + 4 * l) = hi;
                *(uint32_t*)(rb + 64 + 4 * l) = lo;
            }
#pragma unroll
            for (int j = 12; j < 16; j++) {        // zero-pad K 24->32
                *(uint32_t*)(rb + 4 * j) = 0;
                *(uint32_t*)(rb + 64 + 4 * j) = 0;
            }
        }
        __syncwarp();

        // ---------------- layer 1: 24->32 ----------------
#pragma unroll
        for (int mt = 0; mt < 2; mt++) {
            uint32_t Ah0[4], Ah1[4], Al0[4], Al1[4];
            lda(mt, 0, 0, Ah0);  lda(mt, 1, 0, Ah1);
            lda(mt, 0, 64, Al0); lda(mt, 1, 64, Al1);
#pragma unroll
            for (int nt = 0; nt < 4; nt++) {
                float d0 = 0, d1 = 0, d2 = 0, d3 = 0;
                mma_bf16(d0, d1, d2, d3, Ah0, B1h[nt][0]);
                mma_bf16(d0, d1, d2, d3, Ah1, B1h[nt][1]);
                mma_bf16(d0, d1, d2, d3, Ah0, B1l[nt][0]);
                mma_bf16(d0, d1, d2, d3, Ah1, B1l[nt][1]);
                mma_bf16(d0, d1, d2, d3, Al0, B1h[nt][0]);
                mma_bf16(d0, d1, d2, d3, Al1, B1h[nt][1]);
                const float y00 = lrelu(d0 + bl1[nt][0]);
                const float y01 = lrelu(d1 + bl1[nt][1]);
                const float y10 = lrelu(d2 + bl1[nt][0]);
                const float y11 = lrelu(d3 + bl1[nt][1]);
                uint32_t hi, lo;
                char* q = wb + (mt * 16 + qr) * WROW + nt * 16 + qc * 4;
                pkhl(y00, y01, hi, lo);
                *(uint32_t*)q = hi; *(uint32_t*)(q + 64) = lo;
                char* q2 = q + 8 * WROW;
                pkhl(y10, y11, hi, lo);
                *(uint32_t*)q2 = hi; *(uint32_t*)(q2 + 64) = lo;
            }
        }
        __syncwarp();

        // ---------------- layer 2: 32->16 ----------------
#pragma unroll
        for (int mt = 0; mt < 2; mt++) {
            uint32_t Ah0[4], Ah1[4], Al0[4], Al1[4];
            lda(mt, 0, 0, Ah0);  lda(mt, 1, 0, Ah1);
            lda(mt, 0, 64, Al0); lda(mt, 1, 64, Al1);
#pragma unroll
            for (int nt = 0; nt < 2; nt++) {
                float d0 = 0, d1 = 0, d2 = 0, d3 = 0;
                mma_bf16(d0, d1, d2, d3, Ah0, B2h[nt][0]);
                mma_bf16(d0, d1, d2, d3, Ah1, B2h[nt][1]);
                mma_bf16(d0, d1, d2, d3, Ah0, B2l[nt][0]);
                mma_bf16(d0, d1, d2, d3, Ah1, B2l[nt][1]);
                mma_bf16(d0, d1, d2, d3, Al0, B2h[nt][0]);
                mma_bf16(d0, d1, d2, d3, Al1, B2h[nt][1]);
                const float y00 = lrelu(d0 + bl2[nt][0]);
                const float y01 = lrelu(d1 + bl2[nt][1]);
                const float y10 = lrelu(d2 + bl2[nt][0]);
                const float y11 = lrelu(d3 + bl2[nt][1]);
                uint32_t hi, lo;
                char* q = wb + (mt * 16 + qr) * WROW + nt * 16 + qc * 4;
                pkhl(y00, y01, hi, lo);
                *(uint32_t*)q = hi; *(uint32_t*)(q + 64) = lo;
                char* q2 = q + 8 * WROW;
                pkhl(y10, y11, hi, lo);
                *(uint32_t*)q2 = hi; *(uint32_t*)(q2 + 64) = lo;
            }
        }
        __syncwarp();

        // ---------------- layer 3: 16->8  + layer 4 + output ----------------
#pragma unroll
        for (int mt = 0; mt < 2; mt++) {
            uint32_t Ah[4], Al[4];
            lda(mt, 0, 0, Ah);
            lda(mt, 0, 64, Al);
            float d0 = 0, d1 = 0, d2 = 0, d3 = 0;
            mma_bf16(d0, d1, d2, d3, Ah, B3h);
            mma_bf16(d0, d1, d2, d3, Ah, B3l);
            mma_bf16(d0, d1, d2, d3, Al, B3h);
            const float y0 = lrelu(d0 + bl3[0]);
            const float y1 = lrelu(d1 + bl3[1]);
            const float y2 = lrelu(d2 + bl3[0]);
            const float y3 = lrelu(d3 + bl3[1]);
            float p0 = y0 * w4a + y1 * w4b;
            float p1 = y2 * w4a + y3 * w4b;
            p0 += __shfl_xor_sync(0xFFFFFFFFu, p0, 1);
            p0 += __shfl_xor_sync(0xFFFFFFFFu, p0, 2);
            p1 += __shfl_xor_sync(0xFFFFFFFFu, p1, 1);
            p1 += __shfl_xor_sync(0xFFFFFFFFu, p1, 2);
            if (qc == 0) {
                const int r0 = tb + mt * 16 + qr;
                const float z0 = lrelu(lrelu(p0 + b4v));
                const float z1 = lrelu(lrelu(p1 + b4v));
                if (r0 < n)     out[r0]     = z0;
                if (r0 + 8 < n) out[r0 + 8] = z1;
            }
        }
        __syncwarp();
    }
}

extern "C" void kernel_launch(void* const* d_in, const int* in_sizes, int n_in,
                              void* d_out, int out_size)
{
    const float* x      = (const float*)d_in[0];
    const float* tables = (const float*)d_in[1];
    const float* W1 = (const float*)d_in[2];
    const float* b1 = (const float*)d_in[3];
    const float* W2 = (const float*)d_in[4];
    const float* b2 = (const float*)d_in[5];
    const float* W3 = (const float*)d_in[6];
    const float* b3 = (const float*)d_in[7];
    const float* W4 = (const float*)d_in[8];
    const float* b4 = (const float*)d_in[9];
    float* out = (float*)d_out;

    const int n = in_sizes[0] / 2;   // x is [N, 2]
    const int ntiles = (n + 127) / 128;
    int ctas = 148 * 4;
    if (ctas > ntiles) ctas = ntiles;
    nhgrid_mma<<<ctas, 128>>>(x, tables, W1, b1, W2, b2, W3, b3, W4, b4,
                              out, n, ntiles);
}